// round 4
// baseline (speedup 1.0000x reference)
#include <cuda_runtime.h>

// SpatialTransformer: per-batch 3D trilinear warp, faithful to
// transform()+interpn(linear, ij) including the clipped-corner weight quirk:
//   loc0c = clip(floor(loc), 0, max); loc1c = clip(loc0c+1, 0, max)
//   d1 = loc1c - loc  (weight for the FLOOR corner)
//   d0 = 1 - d1       (weight for the CEIL  corner)
//
// R2: fetch each (z,y) row's two x-corners with aligned float4 loads
// (parity trick) to cut L1tex wavefronts ~25%.

#define Bn 2
#define Dn 160
#define Hn 160
#define Wn 160
// C = 2 (float2); rows are Wn float2s = 80 float4s, row bases float4-aligned.

__global__ __launch_bounds__(256)
void st_warp_kernel(const float* __restrict__ vol,
                    const float* __restrict__ trf,
                    float* __restrict__ out)
{
    const int idx = blockIdx.x * blockDim.x + threadIdx.x;   // voxel over B*D*H*W
    constexpr int NVOX = Bn * Dn * Hn * Wn;
    if (idx >= NVOX) return;

    int x = idx % Wn;
    int t = idx / Wn;
    int y = t % Hn;
    t /= Hn;
    int z = t % Dn;
    int b = t / Dn;

    // displacement (stride-3 layout, coalesced across the warp)
    const float sz = __ldg(trf + 3 * idx + 0);
    const float sy = __ldg(trf + 3 * idx + 1);
    const float sx = __ldg(trf + 3 * idx + 2);

    const float lz = (float)z + sz;
    const float ly = (float)y + sy;
    const float lx = (float)x + sx;

    // floor corner, clipped; ceil = clip(floor_clipped + 1)
    float z0f = fminf(fmaxf(floorf(lz), 0.0f), (float)(Dn - 1));
    float y0f = fminf(fmaxf(floorf(ly), 0.0f), (float)(Hn - 1));
    float x0f = fminf(fmaxf(floorf(lx), 0.0f), (float)(Wn - 1));
    float z1f = fminf(z0f + 1.0f, (float)(Dn - 1));
    float y1f = fminf(y0f + 1.0f, (float)(Hn - 1));
    float x1f = fminf(x0f + 1.0f, (float)(Wn - 1));

    // weights: d1 pairs with floor corner, d0 with ceil corner (reference quirk)
    const float dz1 = z1f - lz, dz0 = 1.0f - dz1;
    const float dy1 = y1f - ly, dy0 = 1.0f - dy1;
    const float dx1 = x1f - lx, dx0 = 1.0f - dx1;

    const int z0 = (int)z0f, z1 = (int)z1f;
    const int y0 = (int)y0f, y1 = (int)y1f;
    const int x0 = (int)x0f;

    // Row bases in float2 units; Wn even -> bases even -> float4-index = base>>1.
    const int base_b = b * (Dn * Hn * Wn);
    const int r00 = base_b + (z0 * Hn + y0) * Wn;   // z0,y0
    const int r01 = base_b + (z0 * Hn + y1) * Wn;   // z0,y1
    const int r10 = base_b + (z1 * Hn + y0) * Wn;   // z1,y0
    const int r11 = base_b + (z1 * Hn + y1) * Wn;   // z1,y1

    const float4* __restrict__ v4 = (const float4*)vol;
    const int xq = x0 >> 1;                 // float4 index within row
    const int q00 = (r00 >> 1) + xq;
    const int q01 = (r01 >> 1) + xq;
    const int q10 = (r10 >> 1) + xq;
    const int q11 = (r11 >> 1) + xq;

    // Primary aligned 16B loads, issued together for MLP.
    const float4 a00 = __ldg(v4 + q00);
    const float4 a01 = __ldg(v4 + q01);
    const float4 a10 = __ldg(v4 + q10);
    const float4 a11 = __ldg(v4 + q11);

    const bool odd   = (x0 & 1) != 0;
    const bool need2 = odd & (x0 < Wn - 1);

    // Per-row corner values: c0 at x0, c1 at x1.
    float2 c000, c001, c010, c011, c100, c101, c110, c111;

    if (need2) {
        // Secondary aligned loads (predicated; ~half the lanes).
        const float4 b00 = __ldg(v4 + q00 + 1);
        const float4 b01 = __ldg(v4 + q01 + 1);
        const float4 b10 = __ldg(v4 + q10 + 1);
        const float4 b11 = __ldg(v4 + q11 + 1);
        c000 = make_float2(a00.z, a00.w);  c001 = make_float2(b00.x, b00.y);
        c010 = make_float2(a01.z, a01.w);  c011 = make_float2(b01.x, b01.y);
        c100 = make_float2(a10.z, a10.w);  c101 = make_float2(b10.x, b10.y);
        c110 = make_float2(a11.z, a11.w);  c111 = make_float2(b11.x, b11.y);
    } else if (odd) {
        // x0 == Wn-1 (odd): x1 clamps to x0 -> c1 = c0.
        c000 = make_float2(a00.z, a00.w);  c001 = c000;
        c010 = make_float2(a01.z, a01.w);  c011 = c010;
        c100 = make_float2(a10.z, a10.w);  c101 = c100;
        c110 = make_float2(a11.z, a11.w);  c111 = c110;
    } else {
        // x0 even: float4 holds both corners.
        c000 = make_float2(a00.x, a00.y);  c001 = make_float2(a00.z, a00.w);
        c010 = make_float2(a01.x, a01.y);  c011 = make_float2(a01.z, a01.w);
        c100 = make_float2(a10.x, a10.y);  c101 = make_float2(a10.z, a10.w);
        c110 = make_float2(a11.x, a11.y);  c111 = make_float2(a11.z, a11.w);
    }

    const float w000 = dz1 * dy1 * dx1;
    const float w001 = dz1 * dy1 * dx0;
    const float w010 = dz1 * dy0 * dx1;
    const float w011 = dz1 * dy0 * dx0;
    const float w100 = dz0 * dy1 * dx1;
    const float w101 = dz0 * dy1 * dx0;
    const float w110 = dz0 * dy0 * dx1;
    const float w111 = dz0 * dy0 * dx0;

    float2 o;
    o.x = w000 * c000.x + w001 * c001.x + w010 * c010.x + w011 * c011.x
        + w100 * c100.x + w101 * c101.x + w110 * c110.x + w111 * c111.x;
    o.y = w000 * c000.y + w001 * c001.y + w010 * c010.y + w011 * c011.y
        + w100 * c100.y + w101 * c101.y + w110 * c110.y + w111 * c111.y;

    ((float2*)out)[idx] = o;
}

extern "C" void kernel_launch(void* const* d_in, const int* in_sizes, int n_in,
                              void* d_out, int out_size)
{
    const float* vol = (const float*)d_in[0];
    const float* trf = (const float*)d_in[1];
    float* out = (float*)d_out;

    constexpr int NVOX = Bn * Dn * Hn * Wn;      // 8,192,000
    const int threads = 256;
    const int blocks = (NVOX + threads - 1) / threads;
    st_warp_kernel<<<blocks, threads>>>(vol, trf, out);
}

// round 5
// speedup vs baseline: 1.8843x; 1.8843x over previous
#include <cuda_runtime.h>
#include <cuda_fp16.h>

// SpatialTransformer: per-batch 3D trilinear warp, faithful to
// transform()+interpn(linear, ij) including the clipped-corner weight quirk:
//   loc0c = clip(floor(loc), 0, max); loc1c = clip(loc0c+1, 0, max)
//   d1 = loc1c - loc  (weight for the FLOOR corner)
//   d0 = 1 - d1       (weight for the CEIL  corner)
//
// R5: two-pass scheme.
//  Pass 1 (pack): build a z-pair-packed fp16 volume:
//     g_pack[b][z][y][x] = { half2(vol[b][z][y][x]), half2(vol[b][min(z+1,D-1)][y][x]) }
//     (8 bytes/entry). Streaming, coalesced.
//  Pass 2 (warp): only 4 scattered 8B gathers per output voxel (one per (y,x)
//     corner), each delivering BOTH z corners. Interp math in fp32.
//  Rationale: L1tex wavefronts on scattered gathers are the bottleneck;
//  8B is the sweet-spot width (R4 showed 16B gathers cost ~2x per wavefront).

#define Bn 2
#define Dn 160
#define Hn 160
#define Wn 160

constexpr int NVOX = Bn * Dn * Hn * Wn;      // 8,192,000
constexpr int HWn  = Hn * Wn;

// 8 bytes per voxel: .x = half2 of vol[z] (C=2), .y = half2 of vol[z+1 clamped]
__device__ uint2 g_pack[NVOX];

__global__ __launch_bounds__(256)
void pack_kernel(const float* __restrict__ vol)
{
    const int idx = blockIdx.x * blockDim.x + threadIdx.x;
    if (idx >= NVOX) return;

    const float2 v = __ldg((const float2*)vol + idx);
    const __half2 h = __floats2half2_rn(v.x, v.y);
    const unsigned int hv = *(const unsigned int*)&h;

    // z coordinate of this voxel within its batch
    const int zin = (idx / HWn) % Dn;

    // slot0 of entry z  <- v[z]
    ((unsigned int*)&g_pack[idx])[0] = hv;
    // slot1 of entry z-1 <- v[z]
    if (zin > 0)
        ((unsigned int*)&g_pack[idx - HWn])[1] = hv;
    // clamp: slot1 of entry D-1 <- v[D-1]
    if (zin == Dn - 1)
        ((unsigned int*)&g_pack[idx])[1] = hv;
}

__global__ __launch_bounds__(256)
void st_warp_kernel(const float* __restrict__ trf,
                    float* __restrict__ out)
{
    const int idx = blockIdx.x * blockDim.x + threadIdx.x;   // voxel over B*D*H*W
    if (idx >= NVOX) return;

    int x = idx % Wn;
    int t = idx / Wn;
    int y = t % Hn;
    t /= Hn;
    int z = t % Dn;
    int b = t / Dn;

    // displacement (stride-3 layout, coalesced across the warp)
    const float sz = __ldg(trf + 3 * idx + 0);
    const float sy = __ldg(trf + 3 * idx + 1);
    const float sx = __ldg(trf + 3 * idx + 2);

    const float lz = (float)z + sz;
    const float ly = (float)y + sy;
    const float lx = (float)x + sx;

    // floor corner, clipped; ceil = clip(floor_clipped + 1)
    float z0f = fminf(fmaxf(floorf(lz), 0.0f), (float)(Dn - 1));
    float y0f = fminf(fmaxf(floorf(ly), 0.0f), (float)(Hn - 1));
    float x0f = fminf(fmaxf(floorf(lx), 0.0f), (float)(Wn - 1));
    float z1f = fminf(z0f + 1.0f, (float)(Dn - 1));
    float y1f = fminf(y0f + 1.0f, (float)(Hn - 1));
    float x1f = fminf(x0f + 1.0f, (float)(Wn - 1));

    // weights: d1 pairs with floor corner, d0 with ceil corner (reference quirk)
    const float dz1 = z1f - lz, dz0 = 1.0f - dz1;
    const float dy1 = y1f - ly, dy0 = 1.0f - dy1;
    const float dx1 = x1f - lx, dx0 = 1.0f - dx1;

    const int z0 = (int)z0f;
    const int y0 = (int)y0f, y1 = (int)y1f;
    const int x0 = (int)x0f, x1 = (int)x1f;

    // packed-entry rows (each entry already contains both z corners)
    const int base = b * (Dn * HWn) + z0 * HWn;
    const int ry0 = base + y0 * Wn;
    const int ry1 = base + y1 * Wn;

    // 4 scattered 8B gathers (issued back-to-back for MLP)
    const uint2 p00 = __ldg(&g_pack[ry0 + x0]);
    const uint2 p01 = __ldg(&g_pack[ry0 + x1]);
    const uint2 p10 = __ldg(&g_pack[ry1 + x0]);
    const uint2 p11 = __ldg(&g_pack[ry1 + x1]);

    // z-interpolate each (y,x) corner: f = dz1 * v[z0] + dz0 * v[z1]
    #define ZI(p, f)                                                    \
    {                                                                   \
        const float2 lo = __half22float2(*(const __half2*)&(p).x);      \
        const float2 hi = __half22float2(*(const __half2*)&(p).y);      \
        (f).x = dz1 * lo.x + dz0 * hi.x;                                \
        (f).y = dz1 * lo.y + dz0 * hi.y;                                \
    }
    float2 f00, f01, f10, f11;
    ZI(p00, f00); ZI(p01, f01); ZI(p10, f10); ZI(p11, f11);
    #undef ZI

    const float w00 = dy1 * dx1;   // (y0, x0)
    const float w01 = dy1 * dx0;   // (y0, x1)
    const float w10 = dy0 * dx1;   // (y1, x0)
    const float w11 = dy0 * dx0;   // (y1, x1)

    float2 o;
    o.x = w00 * f00.x + w01 * f01.x + w10 * f10.x + w11 * f11.x;
    o.y = w00 * f00.y + w01 * f01.y + w10 * f10.y + w11 * f11.y;

    ((float2*)out)[idx] = o;
}

extern "C" void kernel_launch(void* const* d_in, const int* in_sizes, int n_in,
                              void* d_out, int out_size)
{
    const float* vol = (const float*)d_in[0];
    const float* trf = (const float*)d_in[1];
    float* out = (float*)d_out;

    const int threads = 256;
    const int blocks = (NVOX + threads - 1) / threads;
    pack_kernel<<<blocks, threads>>>(vol);
    st_warp_kernel<<<blocks, threads>>>(trf, out);
}

// round 6
// speedup vs baseline: 1.9431x; 1.0312x over previous
#include <cuda_runtime.h>
#include <cuda_fp16.h>

// SpatialTransformer: per-batch 3D trilinear warp, faithful to
// transform()+interpn(linear, ij) including the clipped-corner weight quirk:
//   loc0c = clip(floor(loc), 0, max); loc1c = clip(loc0c+1, 0, max)
//   d1 = loc1c - loc  (weight for the FLOOR corner)
//   d0 = 1 - d1       (weight for the CEIL  corner)
//
// R6: z-pair-packed fp16 scratch volume (4 x 8B scattered gathers per voxel,
// the measured L1tex byte-floor), plus:
//   - gather kernel processes the SAME (z,y,x) in both batches per thread:
//     8 gathers in flight, one coordinate decode, -> fewer latency bubbles.
//   - pack kernel does two 8B reads (z, z+1; repeat read L2-hits) and ONE
//     8B store instead of two 4B stores.

#define Bn 2
#define Dn 160
#define Hn 160
#define Wn 160

constexpr int NVOX = Bn * Dn * Hn * Wn;      // 8,192,000
constexpr int HWn  = Hn * Wn;                // 25,600
constexpr int BVOX = Dn * Hn * Wn;           // 4,096,000 (one batch)

// 8 bytes per voxel: .x = half2 of vol[z] (C=2), .y = half2 of vol[z+1 clamped]
__device__ uint2 g_pack[NVOX];

__global__ __launch_bounds__(256)
void pack_kernel(const float* __restrict__ vol)
{
    const int idx = blockIdx.x * blockDim.x + threadIdx.x;
    if (idx >= NVOX) return;

    const int zin = (idx / HWn) % Dn;

    const float2* __restrict__ v2 = (const float2*)vol;
    const float2 lo = __ldg(v2 + idx);
    const int idx_hi = idx + ((zin < Dn - 1) ? HWn : 0);   // clamp z+1 at D-1
    const float2 hi = __ldg(v2 + idx_hi);

    const __half2 hlo = __floats2half2_rn(lo.x, lo.y);
    const __half2 hhi = __floats2half2_rn(hi.x, hi.y);

    uint2 e;
    e.x = *(const unsigned int*)&hlo;
    e.y = *(const unsigned int*)&hhi;
    g_pack[idx] = e;
}

__global__ __launch_bounds__(256)
void st_warp_kernel(const float* __restrict__ trf,
                    float* __restrict__ out)
{
    const int g = blockIdx.x * blockDim.x + threadIdx.x;   // voxel within batch 0
    if (g >= BVOX) return;

    // decode once; both batches share (z,y,x)
    int x = g % Wn;
    int t = g / Wn;
    int y = t % Hn;
    const int z = t / Hn;

    const int idxA = g;            // batch 0
    const int idxB = g + BVOX;     // batch 1

    // displacements (stride-3, coalesced) — issue all 6 loads up front
    const float szA = __ldg(trf + 3 * idxA + 0);
    const float syA = __ldg(trf + 3 * idxA + 1);
    const float sxA = __ldg(trf + 3 * idxA + 2);
    const float szB = __ldg(trf + 3 * idxB + 0);
    const float syB = __ldg(trf + 3 * idxB + 1);
    const float sxB = __ldg(trf + 3 * idxB + 2);

    const float zf = (float)z, yf = (float)y, xf = (float)x;

    // ---- per-voxel coordinate/weight computation ----
    #define COORDS(s_z, s_y, s_x, LZ, LY, LX, DZ1, DZ0, DY1, DY0, DX1, DX0,  \
                   Z0, Y0, Y1, X0, X1)                                       \
        const float LZ = zf + (s_z);                                         \
        const float LY = yf + (s_y);                                         \
        const float LX = xf + (s_x);                                         \
        float z0f_##Z0 = fminf(fmaxf(floorf(LZ), 0.0f), (float)(Dn - 1));    \
        float y0f_##Z0 = fminf(fmaxf(floorf(LY), 0.0f), (float)(Hn - 1));    \
        float x0f_##Z0 = fminf(fmaxf(floorf(LX), 0.0f), (float)(Wn - 1));    \
        float z1f_##Z0 = fminf(z0f_##Z0 + 1.0f, (float)(Dn - 1));            \
        float y1f_##Z0 = fminf(y0f_##Z0 + 1.0f, (float)(Hn - 1));            \
        float x1f_##Z0 = fminf(x0f_##Z0 + 1.0f, (float)(Wn - 1));            \
        const float DZ1 = z1f_##Z0 - LZ, DZ0 = 1.0f - DZ1;                   \
        const float DY1 = y1f_##Z0 - LY, DY0 = 1.0f - DY1;                   \
        const float DX1 = x1f_##Z0 - LX, DX0 = 1.0f - DX1;                   \
        const int Z0 = (int)z0f_##Z0;                                        \
        const int Y0 = (int)y0f_##Z0, Y1 = (int)y1f_##Z0;                    \
        const int X0 = (int)x0f_##Z0, X1 = (int)x1f_##Z0;

    COORDS(szA, syA, sxA, lzA, lyA, lxA, dz1A, dz0A, dy1A, dy0A, dx1A, dx0A,
           z0A, y0A, y1A, x0A, x1A)
    COORDS(szB, syB, sxB, lzB, lyB, lxB, dz1B, dz0B, dy1B, dy0B, dx1B, dx0B,
           z0B, y0B, y1B, x0B, x1B)
    #undef COORDS

    // packed-entry rows; issue all 8 gathers before any consumption
    const int baseA = z0A * HWn;
    const int ry0A = baseA + y0A * Wn;
    const int ry1A = baseA + y1A * Wn;
    const int baseB = BVOX + z0B * HWn;
    const int ry0B = baseB + y0B * Wn;
    const int ry1B = baseB + y1B * Wn;

    const uint2 pA00 = __ldg(&g_pack[ry0A + x0A]);
    const uint2 pA01 = __ldg(&g_pack[ry0A + x1A]);
    const uint2 pA10 = __ldg(&g_pack[ry1A + x0A]);
    const uint2 pA11 = __ldg(&g_pack[ry1A + x1A]);
    const uint2 pB00 = __ldg(&g_pack[ry0B + x0B]);
    const uint2 pB01 = __ldg(&g_pack[ry0B + x1B]);
    const uint2 pB10 = __ldg(&g_pack[ry1B + x0B]);
    const uint2 pB11 = __ldg(&g_pack[ry1B + x1B]);

    // z-interpolate a packed entry: f = dz1 * v[z0] + dz0 * v[z1]
    #define ZI(p, f, DZ1, DZ0)                                          \
    {                                                                   \
        const float2 lo = __half22float2(*(const __half2*)&(p).x);      \
        const float2 hi = __half22float2(*(const __half2*)&(p).y);      \
        (f).x = (DZ1) * lo.x + (DZ0) * hi.x;                            \
        (f).y = (DZ1) * lo.y + (DZ0) * hi.y;                            \
    }
    float2 fA00, fA01, fA10, fA11, fB00, fB01, fB10, fB11;
    ZI(pA00, fA00, dz1A, dz0A); ZI(pA01, fA01, dz1A, dz0A);
    ZI(pA10, fA10, dz1A, dz0A); ZI(pA11, fA11, dz1A, dz0A);
    ZI(pB00, fB00, dz1B, dz0B); ZI(pB01, fB01, dz1B, dz0B);
    ZI(pB10, fB10, dz1B, dz0B); ZI(pB11, fB11, dz1B, dz0B);
    #undef ZI

    {
        const float w00 = dy1A * dx1A, w01 = dy1A * dx0A;
        const float w10 = dy0A * dx1A, w11 = dy0A * dx0A;
        float2 o;
        o.x = w00 * fA00.x + w01 * fA01.x + w10 * fA10.x + w11 * fA11.x;
        o.y = w00 * fA00.y + w01 * fA01.y + w10 * fA10.y + w11 * fA11.y;
        ((float2*)out)[idxA] = o;
    }
    {
        const float w00 = dy1B * dx1B, w01 = dy1B * dx0B;
        const float w10 = dy0B * dx1B, w11 = dy0B * dx0B;
        float2 o;
        o.x = w00 * fB00.x + w01 * fB01.x + w10 * fB10.x + w11 * fB11.x;
        o.y = w00 * fB00.y + w01 * fB01.y + w10 * fB10.y + w11 * fB11.y;
        ((float2*)out)[idxB] = o;
    }
}

extern "C" void kernel_launch(void* const* d_in, const int* in_sizes, int n_in,
                              void* d_out, int out_size)
{
    const float* vol = (const float*)d_in[0];
    const float* trf = (const float*)d_in[1];
    float* out = (float*)d_out;

    const int threads = 256;
    pack_kernel<<<(NVOX + threads - 1) / threads, threads>>>(vol);
    st_warp_kernel<<<(BVOX + threads - 1) / threads, threads>>>(trf, out);
}